// round 3
// baseline (speedup 1.0000x reference)
#include <cuda_runtime.h>

// Problem constants
#define HH   112
#define WW   112
#define CROP 28
#define CW   56
#define NPIX (CW * CW)
#define BB   128
#define MM   64
#define TT   12
#define HID  64
#define OUTD 36

#define ROWS_PER_BLK 8           // crop rows per aux block
#define AUX_PER_B    7           // 7 * 8 = 56 crop rows
#define AUX_BLOCKS   (BB * AUX_PER_B)   // 896
#define MOT_BLOCKS   2
#define NBLK (AUX_BLOCKS + MOT_BLOCKS)  // 898
#define NTHR 256                 // 64 padded cols x 4 groups (2 rows each)

__device__ float g_aux_partial[AUX_BLOCKS];
__device__ float g_mot_partial[MOT_BLOCKS];
__device__ int   g_count = 0;

__global__ __launch_bounds__(NTHR, 6) void fused_kernel(
    const int*   __restrict__ goal_pixel,   // [B,2] (col,row)
    const int*   __restrict__ obj_list,     // [B,M,2] (col,row)
    const int*   __restrict__ obj_num,      // [B]
    const int*   __restrict__ road_mask,    // [B,112,112]
    const float* __restrict__ logits,       // [B,56,56]
    const float* __restrict__ tpos,         // [B,T,2]
    const float* __restrict__ tyaw,         // [B,T]
    const float* __restrict__ w1, const float* __restrict__ b1,
    const float* __restrict__ w2, const float* __restrict__ b2,
    float*       __restrict__ out)
{
    const int blk = blockIdx.x;
    const int tid = threadIdx.x;

    __shared__ float tabc[232];          // tabc[112+d] = exp(-d^2/8)
    __shared__ int2  s_obj[MM];
    __shared__ float colf[MM * 64];      // [m][padded col] col factor (0 if m>=nobj)
    __shared__ float rowf[MM * 8];       // [m][row within octet]
    __shared__ float s_warp[8];
    __shared__ bool  s_last;

    if (blk < AUX_BLOCKS) {
        // ---------------- aux: BCE over 8 crop rows of one batch ----------------
        const int b  = blk / AUX_PER_B;
        const int rb = blk - b * AUX_PER_B;       // row octet index 0..6
        const int ci = tid & 63;                  // padded crop column (valid < 56)
        const int g  = tid >> 6;                  // row pair group 0..3
        const int ri0 = rb * ROWS_PER_BLK;        // first crop row of this block
        const int r0g = ri0 + g * 2;              // this thread's first crop row

        // build centered gaussian table
        if (tid < 232) {
            float d = (float)(tid - 112);
            tabc[tid] = __expf(-d * d * 0.125f);
        }
        const int2* olist = (const int2*)obj_list;
        if (tid < MM) s_obj[tid] = olist[b * MM + tid];
        int nobj = obj_num[b];
        nobj = nobj < 0 ? 0 : (nobj > MM ? MM : nobj);
        const int yg = goal_pixel[2 * b + 0];     // goal col
        const int xg = goal_pixel[2 * b + 1];     // goal row
        __syncthreads();

        // colf[m][ci] = (m<nobj) ? tab[|ci+28 - o.x|] : 0       (4096 entries)
        #pragma unroll
        for (int it = 0; it < 16; it++) {
            const int idx = it * NTHR + tid;
            const int m = idx >> 6, cc = idx & 63;
            const float v = tabc[cc + CROP + 112 - s_obj[m].x];
            colf[idx] = (m < nobj) ? v : 0.0f;
        }
        // rowf[m][j] = tab[|ri0+j+28 - o.y|]                    (512 entries)
        #pragma unroll
        for (int it = 0; it < 2; it++) {
            const int idx = it * NTHR + tid;
            const int m = idx >> 3, j = idx & 7;
            rowf[idx] = tabc[ri0 + j + CROP + 112 - s_obj[m].y];
        }
        __syncthreads();

        // fully unrolled object sum: 2 LDS + 2 FFMA per object
        float s0 = 0.0f, s1 = 0.0f;
        const float*  pcf = colf + ci;
        const float2* prf = (const float2*)(rowf + g * 2);   // stride MM? no: [m*8+g*2]
        #pragma unroll
        for (int m = 0; m < MM; m++) {
            const float  cf = pcf[m * 64];
            const float2 rf = prf[m * 4];        // (m*8 + g*2) floats = m*4 float2
            s0 = fmaf(cf, rf.x, s0);
            s1 = fmaf(cf, rf.y, s1);
        }

        // epilogue: softplus + gt for the 2 pixels
        float local = 0.0f;
        if (ci < CW) {
            const int c = ci + CROP;
            const float gcf = tabc[c + 112 - yg];
            const float gr0 = tabc[r0g + CROP + 112 - xg];
            const float gr1 = tabc[r0g + 1 + CROP + 112 - xg];

            const float* lgp = logits + b * NPIX + r0g * CW + ci;
            const int*   rmp = road_mask + (b * HH + (r0g + CROP)) * WW + c;

            const float z0 = lgp[0],  z1 = lgp[CW];
            const int   m0 = rmp[0],  m1 = rmp[WW];

            const float sp0 = fmaxf(z0, 0.0f) + __logf(1.0f + __expf(-fabsf(z0)));
            const float sp1 = fmaxf(z1, 0.0f) + __logf(1.0f + __expf(-fabsf(z1)));

            float gt0 = (m0 != 0) ? (0.5f + 0.5f * (gcf * gr0) - 0.5f * s0) : 0.0f;
            float gt1 = (m1 != 0) ? (0.5f + 0.5f * (gcf * gr1) - 0.5f * s1) : 0.0f;
            local = (sp0 - z0 * gt0) + (sp1 - z1 * gt1);
        }

        // block reduce (8 warps)
        #pragma unroll
        for (int off = 16; off > 0; off >>= 1)
            local += __shfl_down_sync(0xffffffffu, local, off);
        if ((tid & 31) == 0) s_warp[tid >> 5] = local;
        __syncthreads();
        if (tid == 0) {
            float acc = 0.0f;
            #pragma unroll
            for (int w = 0; w < 8; w++) acc += s_warp[w];
            g_aux_partial[blk] = acc;
        }
    } else {
        // ---------------- motion MLP loss (512 threads over 2 blocks) ----------------
        const int mt = (blk - AUX_BLOCKS) * NTHR + tid;   // 0..511
        float part = 0.0f;
        {
            const int b  = mt >> 2;
            const int og = mt & 3;        // 9 outputs per thread

            const float x0 = (float)goal_pixel[2 * b + 0];
            const float x1 = (float)goal_pixel[2 * b + 1];

            float h[HID];
            #pragma unroll
            for (int j = 0; j < HID; j++) {
                float v = fmaf(x0, w1[j], fmaf(x1, w1[HID + j], b1[j]));
                h[j] = fmaxf(v, 0.0f);
            }
            float acc[9];
            #pragma unroll
            for (int u = 0; u < 9; u++) acc[u] = b2[og * 9 + u];
            for (int j = 0; j < HID; j++) {
                const float hv = h[j];
                const float* wr = w2 + j * OUTD + og * 9;
                #pragma unroll
                for (int u = 0; u < 9; u++)
                    acc[u] = fmaf(hv, wr[u], acc[u]);
            }
            #pragma unroll
            for (int u = 0; u < 9; u++) {
                const int o = og * 9 + u;
                const int t = o / 3, uu = o % 3;
                const float tgt = (uu < 2) ? tpos[(b * TT + t) * 2 + uu]
                                           : tyaw[b * TT + t];
                const float d = acc[u] - tgt;
                part = fmaf(d, d, part);
            }
        }
        #pragma unroll
        for (int off = 16; off > 0; off >>= 1)
            part += __shfl_down_sync(0xffffffffu, part, off);
        if ((tid & 31) == 0) s_warp[tid >> 5] = part;
        __syncthreads();
        if (tid == 0) {
            float acc = 0.0f;
            #pragma unroll
            for (int w = 0; w < 8; w++) acc += s_warp[w];
            g_mot_partial[blk - AUX_BLOCKS] = acc;
        }
    }

    // ---------------- last-block-done final combine ----------------
    __syncthreads();
    __threadfence();
    if (tid == 0) {
        int old = atomicAdd(&g_count, 1);
        s_last = (old == NBLK - 1);
    }
    __syncthreads();

    if (s_last) {
        __threadfence();
        float v = 0.0f;
        // 896 partials: 3 or 4 per thread, fixed order
        for (int i = tid; i < AUX_BLOCKS; i += NTHR)
            v += g_aux_partial[i];
        #pragma unroll
        for (int off = 16; off > 0; off >>= 1)
            v += __shfl_down_sync(0xffffffffu, v, off);
        if ((tid & 31) == 0) s_warp[tid >> 5] = v;
        __syncthreads();
        if (tid == 0) {
            float aux = 0.0f;
            #pragma unroll
            for (int w = 0; w < 8; w++) aux += s_warp[w];
            const float mot = (g_mot_partial[0] + g_mot_partial[1])
                              * (1.0f / (float)(BB * OUTD));
            out[0] = mot + aux;
            out[1] = aux;
            out[2] = mot;
            g_count = 0;   // reset for next graph replay
        }
    }
}

extern "C" void kernel_launch(void* const* d_in, const int* in_sizes, int n_in,
                              void* d_out, int out_size)
{
    const int*   goal_pixel = (const int*)  d_in[0];
    const int*   obj_list   = (const int*)  d_in[1];
    const int*   obj_num    = (const int*)  d_in[2];
    const int*   road_mask  = (const int*)  d_in[3];
    const float* logits     = (const float*)d_in[4];
    const float* tpos       = (const float*)d_in[5];
    const float* tyaw       = (const float*)d_in[6];
    const float* w1         = (const float*)d_in[7];
    const float* b1         = (const float*)d_in[8];
    const float* w2         = (const float*)d_in[9];
    const float* b2         = (const float*)d_in[10];
    float* out = (float*)d_out;

    fused_kernel<<<NBLK, NTHR>>>(goal_pixel, obj_list, obj_num, road_mask,
                                 logits, tpos, tyaw, w1, b1, w2, b2, out);
}

// round 4
// speedup vs baseline: 1.1182x; 1.1182x over previous
#include <cuda_runtime.h>

// Problem constants
#define HH   112
#define WW   112
#define CROP 28
#define CW   56
#define NPIX (CW * CW)
#define BB   128
#define MM   64
#define TT   12
#define HID  64
#define OUTD 36

#define ROWS_BLK   32                    // crop rows per aux block (56..63 dead)
#define AUX_PER_B  2
#define AUX_BLOCKS (BB * AUX_PER_B)      // 256
#define MOT_BLOCKS 2
#define NBLK (AUX_BLOCKS + MOT_BLOCKS)   // 258
#define NTHR 256                         // 64 padded cols x 4 groups (8 rows each)

__device__ float g_aux_partial[AUX_BLOCKS];
__device__ float g_mot_partial[MOT_BLOCKS];
__device__ int   g_count = 0;

__global__ __launch_bounds__(NTHR) void fused_kernel(
    const int*   __restrict__ goal_pixel,   // [B,2] (col,row)
    const int*   __restrict__ obj_list,     // [B,M,2] (col,row)
    const int*   __restrict__ obj_num,      // [B]
    const int*   __restrict__ road_mask,    // [B,112,112]
    const float* __restrict__ logits,       // [B,56,56]
    const float* __restrict__ tpos,         // [B,T,2]
    const float* __restrict__ tyaw,         // [B,T]
    const float* __restrict__ w1, const float* __restrict__ b1,
    const float* __restrict__ w2, const float* __restrict__ b2,
    float*       __restrict__ out)
{
    const int blk = blockIdx.x;
    const int tid = threadIdx.x;

    // tabc[i] = exp(-(i-112)^2/8); naturally underflows to 0 for |i-112|>~27,
    // entries >= ~232 used as guaranteed-zero zone for padded objects.
    __shared__ float tabc[384];
    __shared__ int   s_oxc[MM];          // byte offset: (112 - obj_col)*4
    __shared__ int   s_oyc[MM];          // row index base: rg0 + 112 - obj_row
    __shared__ __align__(16) float rowf[MM * 32];   // [m][row-in-block]
    __shared__ float s_warp[8];
    __shared__ bool  s_last;

    if (blk < AUX_BLOCKS) {
        // ------------- aux: BCE over 32 crop rows of one batch -------------
        const int b   = blk >> 1;
        const int bh  = blk & 1;              // block half
        const int ci  = tid & 63;             // padded crop column (valid <56)
        const int g   = tid >> 6;             // row group 0..3 (8 rows each)
        const int rc0 = bh * ROWS_BLK + g * 8;   // first crop row of this thread
        const int rg0 = CROP + bh * ROWS_BLK;    // first global row of block

        #pragma unroll
        for (int it = 0; it < 2; it++) {
            int i = it * NTHR + tid;
            if (i < 384) {
                float d = (float)(i - 112);
                tabc[i] = __expf(-d * d * 0.125f);
            }
        }
        if (tid < MM) {
            int nobj = obj_num[b];
            nobj = nobj < 0 ? 0 : (nobj > MM ? MM : nobj);
            int2 o = ((const int2*)obj_list)[b * MM + tid];
            if (tid >= nobj) { o.x = -160; o.y = -160; }   // -> zero zone
            s_oxc[tid] = (112 - o.x) * 4;
            s_oyc[tid] = rg0 + 112 - o.y;
        }
        const int yg = goal_pixel[2 * b + 0];
        const int xg = goal_pixel[2 * b + 1];
        __syncthreads();

        // rowf[m][j] = tab value for global row rg0+j vs object m's row
        #pragma unroll
        for (int it = 0; it < 8; it++) {
            const int idx = it * NTHR + tid;
            const int m = idx >> 5, j = idx & 31;
            rowf[idx] = tabc[s_oyc[m] + j];
        }
        __syncthreads();

        // ---- object loop: packed f32x2 accumulation over 8 rows ----
        const char* pt = (const char*)tabc + (CROP + ci) * 4;
        const ulonglong2* prf = (const ulonglong2*)(rowf + g * 8);
        unsigned long long a0 = 0ull, a1 = 0ull, a2 = 0ull, a3 = 0ull;

        #pragma unroll
        for (int mq = 0; mq < 16; mq++) {
            const int4 ox4 = ((const int4*)s_oxc)[mq];
            #pragma unroll
            for (int u = 0; u < 4; u++) {
                const int m = mq * 4 + u;
                const int oxb = (u == 0) ? ox4.x : (u == 1) ? ox4.y
                              : (u == 2) ? ox4.z : ox4.w;
                const float cf = *(const float*)(pt + oxb);
                unsigned long long cfd;
                asm("mov.b64 %0, {%1, %1};" : "=l"(cfd) : "f"(cf));
                const ulonglong2 ra = prf[8 * m];
                const ulonglong2 rb = prf[8 * m + 1];
                asm("fma.rn.f32x2 %0, %1, %2, %0;" : "+l"(a0) : "l"(cfd), "l"(ra.x));
                asm("fma.rn.f32x2 %0, %1, %2, %0;" : "+l"(a1) : "l"(cfd), "l"(ra.y));
                asm("fma.rn.f32x2 %0, %1, %2, %0;" : "+l"(a2) : "l"(cfd), "l"(rb.x));
                asm("fma.rn.f32x2 %0, %1, %2, %0;" : "+l"(a3) : "l"(cfd), "l"(rb.y));
            }
        }

        float s[8];
        asm("mov.b64 {%0, %1}, %2;" : "=f"(s[0]), "=f"(s[1]) : "l"(a0));
        asm("mov.b64 {%0, %1}, %2;" : "=f"(s[2]), "=f"(s[3]) : "l"(a1));
        asm("mov.b64 {%0, %1}, %2;" : "=f"(s[4]), "=f"(s[5]) : "l"(a2));
        asm("mov.b64 {%0, %1}, %2;" : "=f"(s[6]), "=f"(s[7]) : "l"(a3));

        // ---- epilogue: softplus + gt on 8 valid rows ----
        float local = 0.0f;
        if (ci < CW && rc0 < CW) {                     // groups fully valid/dead
            const int c = ci + CROP;
            const float gcf = tabc[c + 112 - yg];
            const float* lgp = logits + b * NPIX + rc0 * CW + ci;
            const int*   rmp = road_mask + (b * HH + (rc0 + CROP)) * WW + c;
            #pragma unroll
            for (int k = 0; k < 8; k++) {
                const float z    = lgp[k * CW];
                const int   road = rmp[k * WW];
                const float sp   = fmaxf(z, 0.0f)
                                 + __logf(1.0f + __expf(-fabsf(z)));
                float gt = 0.0f;
                if (road != 0) {
                    const float gr = tabc[rc0 + k + CROP + 112 - xg];
                    gt = 0.5f + 0.5f * (gcf * gr) - 0.5f * s[k];
                }
                local += sp - z * gt;
            }
        }

        #pragma unroll
        for (int off = 16; off > 0; off >>= 1)
            local += __shfl_down_sync(0xffffffffu, local, off);
        if ((tid & 31) == 0) s_warp[tid >> 5] = local;
        __syncthreads();
        if (tid == 0) {
            float acc = 0.0f;
            #pragma unroll
            for (int w = 0; w < 8; w++) acc += s_warp[w];
            g_aux_partial[blk] = acc;
        }
    } else {
        // ------------- motion MLP loss (512 threads over 2 blocks) -------------
        const int mt = (blk - AUX_BLOCKS) * NTHR + tid;   // 0..511
        float part = 0.0f;
        {
            const int b  = mt >> 2;
            const int og = mt & 3;

            const float x0 = (float)goal_pixel[2 * b + 0];
            const float x1 = (float)goal_pixel[2 * b + 1];

            float h[HID];
            #pragma unroll
            for (int j = 0; j < HID; j++) {
                float v = fmaf(x0, w1[j], fmaf(x1, w1[HID + j], b1[j]));
                h[j] = fmaxf(v, 0.0f);
            }
            float acc[9];
            #pragma unroll
            for (int u = 0; u < 9; u++) acc[u] = b2[og * 9 + u];
            for (int j = 0; j < HID; j++) {
                const float hv = h[j];
                const float* wr = w2 + j * OUTD + og * 9;
                #pragma unroll
                for (int u = 0; u < 9; u++)
                    acc[u] = fmaf(hv, wr[u], acc[u]);
            }
            #pragma unroll
            for (int u = 0; u < 9; u++) {
                const int o = og * 9 + u;
                const int t = o / 3, uu = o % 3;
                const float tgt = (uu < 2) ? tpos[(b * TT + t) * 2 + uu]
                                           : tyaw[b * TT + t];
                const float d = acc[u] - tgt;
                part = fmaf(d, d, part);
            }
        }
        #pragma unroll
        for (int off = 16; off > 0; off >>= 1)
            part += __shfl_down_sync(0xffffffffu, part, off);
        if ((tid & 31) == 0) s_warp[tid >> 5] = part;
        __syncthreads();
        if (tid == 0) {
            float acc = 0.0f;
            #pragma unroll
            for (int w = 0; w < 8; w++) acc += s_warp[w];
            g_mot_partial[blk - AUX_BLOCKS] = acc;
        }
    }

    // ------------- last-block-done final combine -------------
    __syncthreads();
    __threadfence();
    if (tid == 0) {
        int old = atomicAdd(&g_count, 1);
        s_last = (old == NBLK - 1);
    }
    __syncthreads();

    if (s_last) {
        __threadfence();
        float v = 0.0f;
        if (tid < AUX_BLOCKS)              // 256 partials, 1 per thread
            v = g_aux_partial[tid];
        #pragma unroll
        for (int off = 16; off > 0; off >>= 1)
            v += __shfl_down_sync(0xffffffffu, v, off);
        if ((tid & 31) == 0) s_warp[tid >> 5] = v;
        __syncthreads();
        if (tid == 0) {
            float aux = 0.0f;
            #pragma unroll
            for (int w = 0; w < 8; w++) aux += s_warp[w];
            const float mot = (g_mot_partial[0] + g_mot_partial[1])
                              * (1.0f / (float)(BB * OUTD));
            out[0] = mot + aux;
            out[1] = aux;
            out[2] = mot;
            g_count = 0;   // reset for next graph replay
        }
    }
}

extern "C" void kernel_launch(void* const* d_in, const int* in_sizes, int n_in,
                              void* d_out, int out_size)
{
    const int*   goal_pixel = (const int*)  d_in[0];
    const int*   obj_list   = (const int*)  d_in[1];
    const int*   obj_num    = (const int*)  d_in[2];
    const int*   road_mask  = (const int*)  d_in[3];
    const float* logits     = (const float*)d_in[4];
    const float* tpos       = (const float*)d_in[5];
    const float* tyaw       = (const float*)d_in[6];
    const float* w1         = (const float*)d_in[7];
    const float* b1         = (const float*)d_in[8];
    const float* w2         = (const float*)d_in[9];
    const float* b2         = (const float*)d_in[10];
    float* out = (float*)d_out;

    fused_kernel<<<NBLK, NTHR>>>(goal_pixel, obj_list, obj_num, road_mask,
                                 logits, tpos, tyaw, w1, b1, w2, b2, out);
}

// round 5
// speedup vs baseline: 1.8020x; 1.6115x over previous
#include <cuda_runtime.h>

// Problem constants
#define HH   112
#define WW   112
#define CROP 28
#define CW   56
#define NPIX (CW * CW)
#define BB   128
#define MM   64
#define TT   12
#define HID  64
#define OUTD 36

#define NTHR 128
#define AUX_BLOCKS BB            // 1 block per batch
#define MOT_BLOCKS 4
#define NBLK (AUX_BLOCKS + MOT_BLOCKS)   // 132 <= 148 : one wave

__device__ float g_aux_partial[AUX_BLOCKS];
__device__ float g_mot_partial[MOT_BLOCKS];
__device__ int   g_count = 0;

#define FMA2(acc, x, y) \
    asm("fma.rn.f32x2 %0, %1, %2, %0;" : "+l"(acc) : "l"(x), "l"(y))

__global__ __launch_bounds__(NTHR) void fused_kernel(
    const int*   __restrict__ goal_pixel,   // [B,2] (col,row)
    const int*   __restrict__ obj_list,     // [B,M,2] (col,row)
    const int*   __restrict__ obj_num,      // [B]
    const int*   __restrict__ road_mask,    // [B,112,112]
    const float* __restrict__ logits,       // [B,56,56]
    const float* __restrict__ tpos,         // [B,T,2]
    const float* __restrict__ tyaw,         // [B,T]
    const float* __restrict__ w1, const float* __restrict__ b1,
    const float* __restrict__ w2, const float* __restrict__ b2,
    float*       __restrict__ out)
{
    const int blk = blockIdx.x;
    const int tid = threadIdx.x;

    // smem: rowfd first for 16B alignment
    __shared__ __align__(16) unsigned long long rowfd[MM * CW]; // 28KB [m][r] dup'd
    __shared__ __align__(16) float colf[MM * 64];               // 16KB [m][c]
    __shared__ float tabc[384];      // exp(-(i-112)^2/8); zero for far indices
    __shared__ int   s_ox[MM], s_oy[MM];
    __shared__ float s_warp[4];
    __shared__ bool  s_last;

    if (blk < AUX_BLOCKS) {
        // ======== aux: one full 56x56 crop of one batch ========
        const int b  = blk;
        const int rt = tid >> 4;          // row tile 0..7 (7 valid)
        const int ct = tid & 15;          // col tile 0..15 (14 valid)
        const int rteff = (rt < 7) ? rt : 6;

        for (int i = tid; i < 384; i += NTHR) {
            float d = (float)(i - 112);
            tabc[i] = __expf(-d * d * 0.125f);
        }
        if (tid < MM) {
            int nobj = obj_num[b];
            nobj = nobj < 0 ? 0 : (nobj > MM ? MM : nobj);
            int2 o = ((const int2*)obj_list)[b * MM + tid];
            if (tid >= nobj) { o.x = -160; o.y = -160; }  // -> zero zone
            s_ox[tid] = o.x;   // col
            s_oy[tid] = o.y;   // row
        }
        const int yg = goal_pixel[2 * b + 0];
        const int xg = goal_pixel[2 * b + 1];
        __syncthreads();

        // colf[m][c] = tab(c+28 - ox[m]), c in [0,64)
        for (int i = tid; i < MM * 64; i += NTHR) {
            const int m = i >> 6, c = i & 63;
            colf[i] = tabc[c + CROP + 112 - s_ox[m]];
        }
        // rowfd[m][r] = dup(tab(r+28 - oy[m])), r in [0,56)
        for (int i = tid; i < MM * CW; i += NTHR) {
            const int m = i / CW, r = i - m * CW;
            const float v = tabc[r + CROP + 112 - s_oy[m]];
            unsigned long long d;
            asm("mov.b64 %0, {%1, %1};" : "=l"(d) : "f"(v));
            rowfd[i] = d;
        }
        __syncthreads();

        // ======== object loop: 16 f32x2 accumulators, rt-bound FFMA2 ========
        unsigned long long a[16];
        #pragma unroll
        for (int i = 0; i < 16; i++) a[i] = 0ull;

        const ulonglong2* pc = ((const ulonglong2*)colf) + ct;       // + m*16
        const ulonglong2* pr = ((const ulonglong2*)rowfd) + rteff * 4; // + m*28

        #pragma unroll
        for (int m = 0; m < MM; m++) {
            const ulonglong2 cf  = pc[m * 16];      // (c0,c1),(c2,c3)
            const ulonglong2 r01 = pr[m * 28 + 0];  // dup r0, dup r1
            const ulonglong2 r23 = pr[m * 28 + 1];
            const ulonglong2 r45 = pr[m * 28 + 2];
            const ulonglong2 r67 = pr[m * 28 + 3];
            FMA2(a[0],  cf.x, r01.x); FMA2(a[1],  cf.y, r01.x);
            FMA2(a[2],  cf.x, r01.y); FMA2(a[3],  cf.y, r01.y);
            FMA2(a[4],  cf.x, r23.x); FMA2(a[5],  cf.y, r23.x);
            FMA2(a[6],  cf.x, r23.y); FMA2(a[7],  cf.y, r23.y);
            FMA2(a[8],  cf.x, r45.x); FMA2(a[9],  cf.y, r45.x);
            FMA2(a[10], cf.x, r45.y); FMA2(a[11], cf.y, r45.y);
            FMA2(a[12], cf.x, r67.x); FMA2(a[13], cf.y, r67.x);
            FMA2(a[14], cf.x, r67.y); FMA2(a[15], cf.y, r67.y);
        }

        // ======== epilogue: softplus + BCE over this thread's 8x4 tile ========
        float local = 0.0f;
        if (rt < 7 && ct < 14) {
            const int r0 = rt * 8, c0 = ct * 4;
            const float4* lg = (const float4*)(logits + b * NPIX + r0 * CW + c0);
            const int4*   rm = (const int4*)(road_mask
                               + (b * HH + r0 + CROP) * WW + c0 + CROP);
            float gc[4];
            #pragma unroll
            for (int u = 0; u < 4; u++)
                gc[u] = tabc[c0 + u + CROP + 112 - yg];

            #pragma unroll
            for (int k = 0; k < 8; k++) {
                const float4 z4 = lg[k * (CW / 4)];
                const int4   m4 = rm[k * (WW / 4)];
                const float  gr = tabc[r0 + k + CROP + 112 - xg];
                float s[4];
                asm("mov.b64 {%0, %1}, %2;" : "=f"(s[0]), "=f"(s[1]) : "l"(a[2*k]));
                asm("mov.b64 {%0, %1}, %2;" : "=f"(s[2]), "=f"(s[3]) : "l"(a[2*k+1]));
                const float zz[4] = {z4.x, z4.y, z4.z, z4.w};
                const int   mm[4] = {m4.x, m4.y, m4.z, m4.w};
                #pragma unroll
                for (int u = 0; u < 4; u++) {
                    const float z  = zz[u];
                    const float sp = fmaxf(z, 0.0f)
                                   + __logf(1.0f + __expf(-fabsf(z)));
                    float gt = 0.0f;
                    if (mm[u] != 0)
                        gt = 0.5f + 0.5f * (gc[u] * gr) - 0.5f * s[u];
                    local += sp - z * gt;
                }
            }
        }

        #pragma unroll
        for (int off = 16; off > 0; off >>= 1)
            local += __shfl_down_sync(0xffffffffu, local, off);
        if ((tid & 31) == 0) s_warp[tid >> 5] = local;
        __syncthreads();
        if (tid == 0)
            g_aux_partial[blk] = s_warp[0] + s_warp[1] + s_warp[2] + s_warp[3];
    } else {
        // ======== motion MLP loss (512 lanes over 4 blocks) ========
        const int mt = (blk - AUX_BLOCKS) * NTHR + tid;   // 0..511
        float part = 0.0f;
        {
            const int b  = mt >> 2;
            const int og = mt & 3;

            const float x0 = (float)goal_pixel[2 * b + 0];
            const float x1 = (float)goal_pixel[2 * b + 1];

            float h[HID];
            #pragma unroll
            for (int j = 0; j < HID; j++) {
                float v = fmaf(x0, w1[j], fmaf(x1, w1[HID + j], b1[j]));
                h[j] = fmaxf(v, 0.0f);
            }
            float acc[9];
            #pragma unroll
            for (int u = 0; u < 9; u++) acc[u] = b2[og * 9 + u];
            for (int j = 0; j < HID; j++) {
                const float hv = h[j];
                const float* wr = w2 + j * OUTD + og * 9;
                #pragma unroll
                for (int u = 0; u < 9; u++)
                    acc[u] = fmaf(hv, wr[u], acc[u]);
            }
            #pragma unroll
            for (int u = 0; u < 9; u++) {
                const int o = og * 9 + u;
                const int t = o / 3, uu = o % 3;
                const float tgt = (uu < 2) ? tpos[(b * TT + t) * 2 + uu]
                                           : tyaw[b * TT + t];
                const float d = acc[u] - tgt;
                part = fmaf(d, d, part);
            }
        }
        #pragma unroll
        for (int off = 16; off > 0; off >>= 1)
            part += __shfl_down_sync(0xffffffffu, part, off);
        if ((tid & 31) == 0) s_warp[tid >> 5] = part;
        __syncthreads();
        if (tid == 0)
            g_mot_partial[blk - AUX_BLOCKS] =
                s_warp[0] + s_warp[1] + s_warp[2] + s_warp[3];
    }

    // ======== last-block-done final combine ========
    __syncthreads();
    __threadfence();
    if (tid == 0) {
        int old = atomicAdd(&g_count, 1);
        s_last = (old == NBLK - 1);
    }
    __syncthreads();

    if (s_last) {
        __threadfence();
        float v = g_aux_partial[tid];        // 128 partials, 1 per thread
        #pragma unroll
        for (int off = 16; off > 0; off >>= 1)
            v += __shfl_down_sync(0xffffffffu, v, off);
        if ((tid & 31) == 0) s_warp[tid >> 5] = v;
        __syncthreads();
        if (tid == 0) {
            const float aux = s_warp[0] + s_warp[1] + s_warp[2] + s_warp[3];
            const float mot = (g_mot_partial[0] + g_mot_partial[1]
                             + g_mot_partial[2] + g_mot_partial[3])
                              * (1.0f / (float)(BB * OUTD));
            out[0] = mot + aux;
            out[1] = aux;
            out[2] = mot;
            g_count = 0;   // reset for next graph replay
        }
    }
}

extern "C" void kernel_launch(void* const* d_in, const int* in_sizes, int n_in,
                              void* d_out, int out_size)
{
    const int*   goal_pixel = (const int*)  d_in[0];
    const int*   obj_list   = (const int*)  d_in[1];
    const int*   obj_num    = (const int*)  d_in[2];
    const int*   road_mask  = (const int*)  d_in[3];
    const float* logits     = (const float*)d_in[4];
    const float* tpos       = (const float*)d_in[5];
    const float* tyaw       = (const float*)d_in[6];
    const float* w1         = (const float*)d_in[7];
    const float* b1         = (const float*)d_in[8];
    const float* w2         = (const float*)d_in[9];
    const float* b2         = (const float*)d_in[10];
    float* out = (float*)d_out;

    fused_kernel<<<NBLK, NTHR>>>(goal_pixel, obj_list, obj_num, road_mask,
                                 logits, tpos, tyaw, w1, b1, w2, b2, out);
}